// round 16
// baseline (speedup 1.0000x reference)
#include <cuda_runtime.h>

// ===========================================================================
// Packed f32x2 helpers (sm_103a). Halves carry DIFFERENT data (pair0|pair1).
// ===========================================================================
struct f2 { unsigned long long v; };
__device__ __forceinline__ f2 f2fma(f2 a, f2 b, f2 c) {
    f2 r; asm("fma.rn.f32x2 %0, %1, %2, %3;" : "=l"(r.v) : "l"(a.v), "l"(b.v), "l"(c.v)); return r;
}
__device__ __forceinline__ f2 f2mul(f2 a, f2 b) {
    f2 r; asm("mul.rn.f32x2 %0, %1, %2;" : "=l"(r.v) : "l"(a.v), "l"(b.v)); return r;
}
__device__ __forceinline__ f2 f2dup(float x) {
    f2 r; asm("mov.b64 %0, {%1, %1};" : "=l"(r.v) : "f"(x)); return r;
}
__device__ __forceinline__ f2 f2pack(float lo, float hi) {
    f2 r; asm("mov.b64 %0, {%1, %2};" : "=l"(r.v) : "f"(lo), "f"(hi)); return r;
}
__device__ __forceinline__ float2 f2unpack(f2 a) {
    float2 t; asm("mov.b64 {%0, %1}, %2;" : "=f"(t.x), "=f"(t.y) : "l"(a.v)); return t;
}
__device__ __forceinline__ unsigned smem_u32(const void* p) {
    unsigned a; asm("{ .reg .u64 t; cvta.to.shared.u64 t, %1; cvt.u32.u64 %0, t; }"
                    : "=r"(a) : "l"(p)); return a;
}
// Broadcast smem load kept out of the register file (not hoistable).
__device__ __forceinline__ f2 lds_b64(unsigned addr) {
    f2 r; asm volatile("ld.shared.b64 %0, [%1];" : "=l"(r.v) : "r"(addr)); return r;
}

#define N_LAYERS 4
#define BLK 896                         // 28 warps = (igrp 2) x (s 14); 2 tasks/warp
#define XS_PITCH 114                    // floats/img/stage (57 8B units, odd)
#define XS_STAGE (64 * XS_PITCH)        // 7296 floats
#define NSTG 3
#define XS_FLOATS (NSTG * XS_STAGE)     // 21888 floats = 87552 B
#define WS_OFF XS_FLOATS                // float4[1960] = 31360 B
#define LOGIT_OFF (WS_OFF + 1960 * 4)   // float[640]
#define CFS_OFF (LOGIT_OFF + 640)       // float2[18]
#define SMEM_TOTAL ((CFS_OFF + 36) * 4) // 121616 B

// Chebyshev-economized deg-5/4 sin/cos for p in [0,1):
// err ~7e-6 (sin) / ~7e-5 (cos); tol is 1e-3. 6 FMA-pipe ops total.
__device__ __forceinline__ void fsincos2(f2 p, f2& s, f2& c,
        f2 A0, f2 A1, f2 A2, f2 B0, f2 B1, f2 B2) {
    f2 u = f2mul(p, p);
    s = f2mul(p, f2fma(u, f2fma(u, A2, A1), A0));
    c = f2fma(u, f2fma(u, B2, B1), B0);
}

// ZA from register coefficients.
__device__ __forceinline__ f2 bilin2(const f2* q, f2 Ca, f2 Sa, f2 Cb, f2 Sb) {
    f2 t0 = f2fma(q[2], Sb, f2fma(q[1], Cb, q[0]));
    f2 t1 = f2fma(q[5], Sb, f2fma(q[4], Cb, q[3]));
    f2 t2 = f2fma(q[8], Sb, f2fma(q[7], Cb, q[6]));
    return f2fma(t2, Sa, f2fma(t1, Ca, t0));
}

// ZB from smem coefficients (broadcast LDS.64; keeps 18 regs free).
__device__ __forceinline__ f2 bilin_s(unsigned cfa, f2 Ca, f2 Sa, f2 Cb, f2 Sb) {
    f2 t0 = f2fma(lds_b64(cfa + 16), Sb, f2fma(lds_b64(cfa + 8),  Cb, lds_b64(cfa)));
    f2 t1 = f2fma(lds_b64(cfa + 40), Sb, f2fma(lds_b64(cfa + 32), Cb, lds_b64(cfa + 24)));
    f2 t2 = f2fma(lds_b64(cfa + 64), Sb, f2fma(lds_b64(cfa + 56), Cb, lds_b64(cfa + 48)));
    return f2fma(t2, Sa, f2fma(t1, Ca, t0));
}

// Fold one wire-pair's ansatz into its 4x4 orthogonal matrix M (MUFU trig).
__device__ void fold_M(const float* __restrict__ params, int pair, float M[4][4]) {
    for (int r = 0; r < 4; r++)
        for (int c = 0; c < 4; c++) M[r][c] = (r == c) ? 1.f : 0.f;
    for (int l = 0; l < N_LAYERS; ++l) {
        float a = 0.5f * params[l * 4 + 2 * pair];
        float b = 0.5f * params[l * 4 + 2 * pair + 1];
        float ca = __cosf(a), sa = __sinf(a), cb = __cosf(b), sb = __sinf(b);
        float Ra[2][2] = {{ca, -sa}, {sa, ca}};
        float Rb[2][2] = {{cb, -sb}, {sb, cb}};
        float R[4][4];
        for (int i = 0; i < 2; i++)
            for (int j = 0; j < 2; j++)
                for (int k = 0; k < 2; k++)
                    for (int m = 0; m < 2; m++)
                        R[2*i+j][2*k+m] = Ra[i][k] * Rb[j][m];
        float Nm[4][4];
        for (int r = 0; r < 4; r++)
            for (int c = 0; c < 4; c++) {
                float s = 0.f;
                for (int t = 0; t < 4; t++) s += R[r][t] * M[t][c];
                Nm[r][c] = s;
            }
        for (int c = 0; c < 4; c++) {   // CX: swap rows 2,3
            M[0][c] = Nm[0][c]; M[1][c] = Nm[1][c];
            M[2][c] = Nm[3][c]; M[3][c] = Nm[2][c];
        }
    }
}

// One coefficient coef[pair][jw][aa*3+bb] from the folded M.
__device__ float coef_from_M(const float M[4][4], int jw, int aa, int bb) {
    const float AL[2][2][3] = {
        {{0.5f, 0.5f, 0.f}, {0.f, 0.f, 0.5f}},
        {{0.f, 0.f, 0.5f}, {0.5f, -0.5f, 0.f}}
    };
    float s = 0.f;
    for (int i = 0; i < 2; i++)
        for (int k = 0; k < 2; k++)
            for (int j = 0; j < 2; j++)
                for (int m = 0; m < 2; m++) {
                    float q = 0.f;
                    for (int t = 0; t < 4; t++) {
                        float d = (jw == 0) ? ((t < 2) ? 1.f : -1.f)
                                            : ((t & 1) ? -1.f : 1.f);
                        q += d * M[t][2*i+j] * M[t][2*k+m];
                    }
                    s += q * AL[i][k][aa] * AL[j][m][bb];
                }
    return s;
}

// ===========================================================================
// Single fused kernel: 896 thr = 28 warps = (igrp 2, s 14); 64 images/block.
// 7 warps/SMSP; exactly 2 tasks/warp/step (perfect balance). ZA coefs in
// regs, ZB coefs via broadcast LDS to fit the 72-reg cap. Staging spread
// over all 896 threads (4 cp.asyncs each; 896 = 16*56, div-free).
// ===========================================================================
__global__ void __launch_bounds__(BLK, 1)
quanv_kernel(const float* __restrict__ x, const float* __restrict__ params,
             const float* __restrict__ W, const float* __restrict__ bias,
             float* __restrict__ out) {
    extern __shared__ __align__(16) float smemf[];
    float*  xs      = smemf;                         // [3][64][114]
    float4* Ws4     = (float4*)(smemf + WS_OFF);     // [1960]
    float*  logit_s = smemf + LOGIT_OFF;             // [64][10]
    float2* cfs     = (float2*)(smemf + CFS_OFF);    // [18] (pair0, pair1)
    f2*     red     = (f2*)smemf;                     // alias of xs after compute

    const int tid = threadIdx.x, w = tid >> 5, lane = tid & 31;
    const int igrp = w / 14, s = w - 14 * igrp;      // s in 0..13
    const long img0 = (long)blockIdx.x * 64;
    const unsigned xs_b = smem_u32(xs);

    // --- staging map: all 896 threads, 4 chunks each (896 = 16*56) ---
    const int j0 = tid / 56, c0 = tid - 56 * j0;     // j0 in 0..15
    const float* sbase = x + (img0 + j0) * 784 + 2 * c0;
    const unsigned dbase = xs_b + (unsigned)(j0 * XS_PITCH + 2 * c0) * 4u;

    // --- prologue: issue stages 0,1 ---
    {
        const float* src = sbase;
        unsigned dst = dbase;
#pragma unroll
        for (int i = 0; i < 4; ++i) {
            asm volatile("cp.async.ca.shared.global [%0], [%1], 8;" :: "r"(dst), "l"(src));
            src += 16 * 784; dst += 16 * XS_PITCH * 4;
        }
        asm volatile("cp.async.commit_group;");
        src = sbase + 112;
        dst = dbase + XS_STAGE * 4u;
#pragma unroll
        for (int i = 0; i < 4; ++i) {
            asm volatile("cp.async.ca.shared.global [%0], [%1], 8;" :: "r"(dst), "l"(src));
            src += 16 * 784; dst += 16 * XS_PITCH * 4;
        }
        asm volatile("cp.async.commit_group;");
    }

    // --- coefficients (threads 0..17) + W pack, hidden behind prologue ---
    if (tid < 18) {
        const int jw = tid / 9, aa = (tid % 9) / 3, bb = tid % 3;
        float M0[4][4], M1[4][4];
        fold_M(params, 0, M0);
        fold_M(params, 1, M1);
        cfs[tid] = make_float2(coef_from_M(M0, jw, aa, bb),
                               coef_from_M(M1, jw, aa, bb));
    }
    for (int i = tid; i < 1960; i += BLK) {
        int p = i / 10, c = i - 10 * p;
        const float* wr = W + c * 784 + 4 * p;
        Ws4[i] = make_float4(wr[0], wr[2], wr[1], wr[3]);  // (w0,w2 | w1,w3)
    }
    __syncthreads();                     // cfs/Ws visible before reg loads

    // Economized poly constants (basis u = p^2 on [0,1)).
    const f2 A0 = f2dup(0.99999380f), A1 = f2dup(-0.16655506f), A2 = f2dup(8.0357143e-3f);
    const f2 B0 = f2dup(0.99995660f), B1 = f2dup(-0.49921875f), B2 = f2dup(3.9583333e-2f);

    f2 cfbA[9];                          // ZA coefficients (Z0|Z2) in registers
#pragma unroll
    for (int i = 0; i < 9; ++i)
        cfbA[i].v = *(const unsigned long long*)&cfs[i];
    const unsigned cfB = smem_u32(cfs) + 72;   // ZB coefficients in smem

    f2 acc[10];
#pragma unroll
    for (int c = 0; c < 10; ++c) acc[c] = f2dup(0.f);

    // warp s owns tasks 2s, 2s+1 (adjacent patch columns, same row)
    const int prl = s / 7;                        // 0 or 1
    const int pc0 = 2 * (s - 7 * prl);            // 0,2,..,12
    const int xo0 = prl * 56 + 2 * pc0;           // task0 x offset; task1 = +2
    const int img_local = igrp * 32 + lane;

#pragma unroll 1
    for (int r = 0; r < 7; ++r) {
        asm volatile("cp.async.wait_group 1;");
        __syncthreads();                 // stage r visible; compute r-1 done
        if (r + 2 < 7) {
            const float* src = sbase + (r + 2) * 112;
            unsigned dst = dbase + ((r + 2) % NSTG) * (XS_STAGE * 4u);
#pragma unroll
            for (int i = 0; i < 4; ++i) {
                asm volatile("cp.async.ca.shared.global [%0], [%1], 8;" :: "r"(dst), "l"(src));
                src += 16 * 784; dst += 16 * XS_PITCH * 4;
            }
        }
        asm volatile("cp.async.commit_group;");

        const float* xb = xs + (r % NSTG) * XS_STAGE + img_local * XS_PITCH + xo0;
        const float4* wp = Ws4 + ((2 * r + prl) * 14 + pc0) * 10;

        // load both tasks' pixels up front (hide LDS latency under task0)
        float2 top0 = *(const float2*)xb;
        float2 bot0 = *(const float2*)(xb + 28);
        float2 top1 = *(const float2*)(xb + 2);
        float2 bot1 = *(const float2*)(xb + 30);

#define TASK_COMPUTE(TOP, BOT, WPTR)                                           \
        {                                                                      \
            f2 pa = f2pack((TOP).x, (BOT).x);           /* (wire0 | wire2) */  \
            f2 pb = f2pack((TOP).y, (BOT).y);           /* (wire1 | wire3) */  \
            f2 Sa, Ca, Sb, Cb;                                                 \
            fsincos2(pa, Sa, Ca, A0, A1, A2, B0, B1, B2);                      \
            fsincos2(pb, Sb, Cb, A0, A1, A2, B0, B1, B2);                      \
            f2 ZA = bilin2(cfbA, Ca, Sa, Cb, Sb);       /* (Z0 | Z2) */        \
            f2 ZB = bilin_s(cfB, Ca, Sa, Cb, Sb);       /* (Z1 | Z3) */        \
            _Pragma("unroll")                                                  \
            for (int c = 0; c < 10; ++c) {                                     \
                ulonglong2 wv = *(const ulonglong2*)((WPTR) + c);              \
                f2 wA; wA.v = wv.x;                     /* (w0 | w2) */        \
                f2 wB; wB.v = wv.y;                     /* (w1 | w3) */        \
                acc[c] = f2fma(wA, ZA, f2fma(wB, ZB, acc[c]));                 \
            }                                                                  \
        }

        TASK_COMPUTE(top0, bot0, wp)
        TASK_COMPUTE(top1, bot1, wp + 10)
#undef TASK_COMPUTE
    }

    asm volatile("cp.async.wait_group 0;");
    __syncthreads();                     // all compute done before xs reused

#pragma unroll
    for (int c = 0; c < 10; ++c) red[tid * 10 + c] = acc[c];
    __syncthreads();

    // tid = (img 0..63, class 0..9): sum 14 s-partials; halves = pair0+pair1
    if (tid < 640) {
        const int img = tid / 10, c = tid - 10 * img;
        const int g = img >> 5, j = img & 31;
        float sum = bias[c];
#pragma unroll
        for (int sp = 0; sp < 14; ++sp) {
            float2 tv = f2unpack(red[((g * 14 + sp) * 32 + j) * 10 + c]);
            sum += tv.x + tv.y;
        }
        logit_s[img * 10 + c] = sum;
    }
    __syncthreads();

    if (tid < 64) {
        float v[10], m = -1e30f;
#pragma unroll
        for (int c = 0; c < 10; ++c) { v[c] = logit_s[tid * 10 + c]; m = fmaxf(m, v[c]); }
        float se = 0.f;
#pragma unroll
        for (int c = 0; c < 10; ++c) se += __expf(v[c] - m);
        const float lse = m + __logf(se);
        const long im = img0 + tid;
#pragma unroll
        for (int c = 0; c < 10; ++c) out[im * 10 + c] = v[c] - lse;
    }
}

extern "C" void kernel_launch(void* const* d_in, const int* in_sizes, int n_in,
                              void* d_out, int out_size) {
    const float* x      = (const float*)d_in[0];  // (8192, 784)
    const float* params = (const float*)d_in[1];  // (4, 4)
    const float* W      = (const float*)d_in[2];  // (10, 784)
    const float* bias   = (const float*)d_in[3];  // (10,)
    float* out = (float*)d_out;

    cudaFuncSetAttribute(quanv_kernel,
                         cudaFuncAttributeMaxDynamicSharedMemorySize, SMEM_TOTAL);
    const int bsz = in_sizes[0] / 784;
    quanv_kernel<<<bsz / 64, BLK, SMEM_TOTAL>>>(x, params, W, bias, out);
}